// round 7
// baseline (speedup 1.0000x reference)
#include <cuda_runtime.h>

#define B_   2
#define T_   8
#define N_   50000
#define C_   64
#define HID_ 128
#define R_   16
#define L_   12
#define E_   1600000

using u64 = unsigned long long;

// Scratch for per-node MLP outputs a,b: (B, N, R) fp32 each.
__device__ float g_a[B_ * N_ * R_];
__device__ float g_b[B_ * N_ * R_];

// ---- packed f32x2 helpers (sm_100+; SASS FFMA2 path only reachable via PTX) ----
__device__ __forceinline__ u64 pk(float lo, float hi) {
    u64 r; asm("mov.b64 %0, {%1, %2};" : "=l"(r) : "f"(lo), "f"(hi)); return r;
}
__device__ __forceinline__ void unpk(u64 v, float& lo, float& hi) {
    asm("mov.b64 {%0, %1}, %2;" : "=f"(lo), "=f"(hi) : "l"(v));
}
__device__ __forceinline__ u64 ff2(u64 a, u64 b, u64 c) {
    u64 d; asm("fma.rn.f32x2 %0, %1, %2, %3;" : "=l"(d) : "l"(a), "l"(b), "l"(c)); return d;
}
__device__ __forceinline__ u64 mm2(u64 a, u64 b) {
    u64 d; asm("mul.rn.f32x2 %0, %1, %2;" : "=l"(d) : "l"(a), "l"(b)); return d;
}

// ============================================================================
// Kernel 1: per-node 2-layer MLP.  grid.y = 0 -> (s weights -> g_a),
//                                  grid.y = 1 -> (d weights -> g_b).
// One thread = one node. __launch_bounds__(128, 4) caps regs at 128 so 4 CTAs
// fit per SM (16 warps) — without the minBlocks hint ptxas allocated ~200 regs
// and occupancy collapsed to 2 CTAs, exposing FFMA2/LDS latency.
// ============================================================================
__global__ __launch_bounds__(128, 4) void mlp_kernel(
    const float* __restrict__ X,
    const float* __restrict__ W1s, const float* __restrict__ b1s,
    const float* __restrict__ W2s, const float* __restrict__ b2s,
    const float* __restrict__ W1d, const float* __restrict__ b1d,
    const float* __restrict__ W2d, const float* __restrict__ b2d)
{
    const int which = blockIdx.y;
    const float* W1 = which ? W1d : W1s;
    const float* b1 = which ? b1d : b1s;
    const float* W2 = which ? W2d : W2s;
    const float* b2 = which ? b2d : b2s;
    float* outp     = which ? g_b : g_a;

    // W1 packed over K: W1p[kp*HID + h] = {W1[2kp][h], W1[2kp+1][h]}   (32 KB)
    // W2 packed over R: W2p[j*8 + rp]   = {W2[j][2rp], W2[j][2rp+1]}   ( 8 KB)
    __shared__ __align__(16) u64   W1p[(C_ / 2) * HID_];
    __shared__ __align__(16) u64   W2p[HID_ * (R_ / 2)];
    __shared__ float b1sm[HID_];
    __shared__ u64   b2p[R_ / 2];

    const int t = threadIdx.x;
    for (int i = t; i < (C_ / 2) * HID_; i += 128) {
        int kp = i >> 7, h = i & 127;
        W1p[i] = pk(W1[(2 * kp) * HID_ + h], W1[(2 * kp + 1) * HID_ + h]);
    }
    for (int i = t; i < HID_ * (R_ / 2); i += 128)
        W2p[i] = ((const u64*)W2)[i];           // pairs over r are contiguous
    if (t < HID_)   b1sm[t] = b1[t];
    if (t < R_ / 2) b2p[t]  = ((const u64*)b2)[t];
    __syncthreads();

    const int n_global = blockIdx.x * 128 + t;
    if (n_global >= B_ * N_) return;
    const int bb = (n_global >= N_) ? 1 : 0;
    const int n  = n_global - bb * N_;

    // H row = X[bb, T-1, n, :], contiguous 64 floats = 32 packed pairs.
    const ulonglong2* xrow = (const ulonglong2*)
        (X + ((size_t)bb * T_ + (T_ - 1)) * (size_t)N_ * C_ + (size_t)n * C_);
    u64 x2[32];
    #pragma unroll
    for (int i = 0; i < 16; i++) { ulonglong2 v = xrow[i]; x2[2*i] = v.x; x2[2*i+1] = v.y; }

    u64 out2[8];
    #pragma unroll
    for (int r = 0; r < 8; r++) out2[r] = b2p[r];

    #pragma unroll 1
    for (int c = 0; c < 8; c++) {                 // 8 chunks of 16 hidden units
        u64 acc2[16];
        #pragma unroll
        for (int j = 0; j < 16; j++) acc2[j] = 0ull;   // {0.f, 0.f}

        #pragma unroll
        for (int kp = 0; kp < 32; kp++) {
            // broadcast LDS.128: two k-pair weights per load
            const ulonglong2* wrow = (const ulonglong2*)&W1p[kp * HID_ + c * 16];
            #pragma unroll
            for (int jq = 0; jq < 8; jq++) {
                ulonglong2 w = wrow[jq];
                acc2[2*jq]     = ff2(x2[kp], w.x, acc2[2*jq]);
                acc2[2*jq + 1] = ff2(x2[kp], w.y, acc2[2*jq + 1]);
            }
        }
        // finish hidden units: horizontal add + bias + relu, then layer 2
        #pragma unroll
        for (int j = 0; j < 16; j++) {
            float lo, hi; unpk(acc2[j], lo, hi);
            float h = lo + hi + b1sm[c * 16 + j];
            h = fmaxf(h, 0.f);
            u64 h2 = pk(h, h);
            const ulonglong2* w2row = (const ulonglong2*)&W2p[(c * 16 + j) * 8];
            #pragma unroll
            for (int rq = 0; rq < 4; rq++) {
                ulonglong2 w = w2row[rq];
                out2[2*rq]     = ff2(h2, w.x, out2[2*rq]);
                out2[2*rq + 1] = ff2(h2, w.y, out2[2*rq + 1]);
            }
        }
    }

    u64* orow = (u64*)(outp + (size_t)n_global * R_);
    #pragma unroll
    for (int r = 0; r < 8; r++) orow[r] = out2[r];
}

// ============================================================================
// Kernel 2: edge scoring, one edge per thread.
// __launch_bounds__(256, 4) caps regs at 64: without the minBlocks hint ptxas
// burned 246 regs pipelining both batches and occupancy stuck at 1 CTA/SM.
// 4 CTAs/SM = 32 warps gives enough MLP to hit the L2 gather throughput bound.
// logits[b,l,e] = sum_r gamma[l,r] * a[b,I[e],r] * b[b,J[e],r]
// ============================================================================
__global__ __launch_bounds__(256, 4) void edge_kernel(
    const int* __restrict__ eidx,
    const float* __restrict__ gamma,
    float* __restrict__ out)
{
    __shared__ u64 g2[L_ * (R_ / 2)];     // gamma as pairs over r
    const int t = threadIdx.x;
    if (t < L_ * (R_ / 2)) g2[t] = ((const u64*)gamma)[t];
    __syncthreads();

    const int e = blockIdx.x * 256 + t;
    if (e >= E_) return;

    const int I = eidx[e];
    const int J = eidx[(size_t)E_ + e];

    #pragma unroll 1
    for (int b = 0; b < 2; b++) {
        const ulonglong2* ar = (const ulonglong2*)&g_a[((size_t)b * N_ + I) * R_];
        const ulonglong2* br = (const ulonglong2*)&g_b[((size_t)b * N_ + J) * R_];
        u64 p2[8];
        #pragma unroll
        for (int q = 0; q < 4; q++) {
            ulonglong2 av = ar[q], bv = br[q];
            p2[2*q]     = mm2(av.x, bv.x);
            p2[2*q + 1] = mm2(av.y, bv.y);
        }
        float* ob = out + (size_t)b * L_ * E_ + e;
        #pragma unroll
        for (int l = 0; l < L_; l++) {
            u64 acc = 0ull;
            #pragma unroll
            for (int r = 0; r < 8; r++)
                acc = ff2(g2[l * 8 + r], p2[r], acc);
            float lo, hi; unpk(acc, lo, hi);
            ob[(size_t)l * E_] = lo + hi;
        }
    }
}

extern "C" void kernel_launch(void* const* d_in, const int* in_sizes, int n_in,
                              void* d_out, int out_size) {
    const float* X    = (const float*)d_in[0];
    const int*   eidx = (const int*)d_in[1];           // int32 (jax demotes int64)
    const float* W1s  = (const float*)d_in[2];
    const float* b1s  = (const float*)d_in[3];
    const float* W2s  = (const float*)d_in[4];
    const float* b2s  = (const float*)d_in[5];
    const float* W1d  = (const float*)d_in[6];
    const float* b1d  = (const float*)d_in[7];
    const float* W2d  = (const float*)d_in[8];
    const float* b2d  = (const float*)d_in[9];
    const float* gam  = (const float*)d_in[10];
    float* out = (float*)d_out;

    dim3 g1((B_ * N_ + 127) / 128, 2);
    mlp_kernel<<<g1, 128>>>(X, W1s, b1s, W2s, b2s, W1d, b1d, W2d, b2d);

    edge_kernel<<<(E_ + 255) / 256, 256>>>(eidx, gam, out);
}

// round 8
// speedup vs baseline: 1.6954x; 1.6954x over previous
#include <cuda_runtime.h>

#define B_   2
#define T_   8
#define N_   50000
#define C_   64
#define HID_ 128
#define R_   16
#define L_   12
#define E_   1600000

using u64 = unsigned long long;

// Scratch for per-node MLP outputs a,b: (B, N, R) fp32 each. 12.8 MB total —
// must stay L2-resident during edge_kernel (written L2-warm by mlp_kernel).
__device__ float g_a[B_ * N_ * R_];
__device__ float g_b[B_ * N_ * R_];

// ---- packed f32x2 helpers (sm_100+; SASS FFMA2 path only reachable via PTX) ----
__device__ __forceinline__ u64 pk(float lo, float hi) {
    u64 r; asm("mov.b64 %0, {%1, %2};" : "=l"(r) : "f"(lo), "f"(hi)); return r;
}
__device__ __forceinline__ void unpk(u64 v, float& lo, float& hi) {
    asm("mov.b64 {%0, %1}, %2;" : "=f"(lo), "=f"(hi) : "l"(v));
}
__device__ __forceinline__ u64 ff2(u64 a, u64 b, u64 c) {
    u64 d; asm("fma.rn.f32x2 %0, %1, %2, %3;" : "=l"(d) : "l"(a), "l"(b), "l"(c)); return d;
}
__device__ __forceinline__ u64 mm2(u64 a, u64 b) {
    u64 d; asm("mul.rn.f32x2 %0, %1, %2;" : "=l"(d) : "l"(a), "l"(b)); return d;
}
// Streaming store (evict-first): output stream must NOT thrash g_a/g_b out of L2.
__device__ __forceinline__ void stcs(float* p, float v) {
    asm volatile("st.global.cs.f32 [%0], %1;" :: "l"(p), "f"(v) : "memory");
}

// ============================================================================
// Kernel 1: per-node 2-layer MLP.  grid.y = 0 -> (s weights -> g_a),
//                                  grid.y = 1 -> (d weights -> g_b).
// One thread = one node. __launch_bounds__(128, 3) = 168-reg cap: live state
// (x2[64] + acc2[32] + out2[16] + temps ~ 135 regs) fits WITHOUT spilling —
// the previous (128,4)=128-reg cap forced local-memory spills.
// ============================================================================
__global__ __launch_bounds__(128, 3) void mlp_kernel(
    const float* __restrict__ X,
    const float* __restrict__ W1s, const float* __restrict__ b1s,
    const float* __restrict__ W2s, const float* __restrict__ b2s,
    const float* __restrict__ W1d, const float* __restrict__ b1d,
    const float* __restrict__ W2d, const float* __restrict__ b2d)
{
    const int which = blockIdx.y;
    const float* W1 = which ? W1d : W1s;
    const float* b1 = which ? b1d : b1s;
    const float* W2 = which ? W2d : W2s;
    const float* b2 = which ? b2d : b2s;
    float* outp     = which ? g_b : g_a;

    // W1 packed over K: W1p[kp*HID + h] = {W1[2kp][h], W1[2kp+1][h]}   (32 KB)
    // W2 packed over R: W2p[j*8 + rp]   = {W2[j][2rp], W2[j][2rp+1]}   ( 8 KB)
    __shared__ __align__(16) u64   W1p[(C_ / 2) * HID_];
    __shared__ __align__(16) u64   W2p[HID_ * (R_ / 2)];
    __shared__ float b1sm[HID_];
    __shared__ u64   b2p[R_ / 2];

    const int t = threadIdx.x;
    for (int i = t; i < (C_ / 2) * HID_; i += 128) {
        int kp = i >> 7, h = i & 127;
        W1p[i] = pk(W1[(2 * kp) * HID_ + h], W1[(2 * kp + 1) * HID_ + h]);
    }
    for (int i = t; i < HID_ * (R_ / 2); i += 128)
        W2p[i] = ((const u64*)W2)[i];           // pairs over r are contiguous
    if (t < HID_)   b1sm[t] = b1[t];
    if (t < R_ / 2) b2p[t]  = ((const u64*)b2)[t];
    __syncthreads();

    const int n_global = blockIdx.x * 128 + t;
    if (n_global >= B_ * N_) return;
    const int bb = (n_global >= N_) ? 1 : 0;
    const int n  = n_global - bb * N_;

    // H row = X[bb, T-1, n, :], contiguous 64 floats = 32 packed pairs.
    const ulonglong2* xrow = (const ulonglong2*)
        (X + ((size_t)bb * T_ + (T_ - 1)) * (size_t)N_ * C_ + (size_t)n * C_);
    u64 x2[32];
    #pragma unroll
    for (int i = 0; i < 16; i++) { ulonglong2 v = xrow[i]; x2[2*i] = v.x; x2[2*i+1] = v.y; }

    u64 out2[8];
    #pragma unroll
    for (int r = 0; r < 8; r++) out2[r] = b2p[r];

    #pragma unroll 1
    for (int c = 0; c < 8; c++) {                 // 8 chunks of 16 hidden units
        u64 acc2[16];
        #pragma unroll
        for (int j = 0; j < 16; j++) acc2[j] = 0ull;   // {0.f, 0.f}

        #pragma unroll
        for (int kp = 0; kp < 32; kp++) {
            // broadcast LDS.128: two k-pair weights per load
            const ulonglong2* wrow = (const ulonglong2*)&W1p[kp * HID_ + c * 16];
            #pragma unroll
            for (int jq = 0; jq < 8; jq++) {
                ulonglong2 w = wrow[jq];
                acc2[2*jq]     = ff2(x2[kp], w.x, acc2[2*jq]);
                acc2[2*jq + 1] = ff2(x2[kp], w.y, acc2[2*jq + 1]);
            }
        }
        // finish hidden units: horizontal add + bias + relu, then layer 2
        #pragma unroll
        for (int j = 0; j < 16; j++) {
            float lo, hi; unpk(acc2[j], lo, hi);
            float h = lo + hi + b1sm[c * 16 + j];
            h = fmaxf(h, 0.f);
            u64 h2 = pk(h, h);
            const ulonglong2* w2row = (const ulonglong2*)&W2p[(c * 16 + j) * 8];
            #pragma unroll
            for (int rq = 0; rq < 4; rq++) {
                ulonglong2 w = w2row[rq];
                out2[2*rq]     = ff2(h2, w.x, out2[2*rq]);
                out2[2*rq + 1] = ff2(h2, w.y, out2[2*rq + 1]);
            }
        }
    }

    u64* orow = (u64*)(outp + (size_t)n_global * R_);
    #pragma unroll
    for (int r = 0; r < 8; r++) orow[r] = out2[r];
}

// ============================================================================
// Kernel 2: edge scoring, one edge per thread, 4 CTAs/SM.
// Gathers from g_a/g_b rely on L2 residency; output uses st.global.cs
// (evict-first) so the 153.6 MB store stream cannot evict the 12.8 MB
// gather working set (R7 showed exactly that thrash: 1.05 GB DRAM traffic).
// logits[b,l,e] = sum_r gamma[l,r] * a[b,I[e],r] * b[b,J[e],r]
// ============================================================================
__global__ __launch_bounds__(256, 4) void edge_kernel(
    const int* __restrict__ eidx,
    const float* __restrict__ gamma,
    float* __restrict__ out)
{
    __shared__ u64 g2[L_ * (R_ / 2)];     // gamma as pairs over r
    const int t = threadIdx.x;
    if (t < L_ * (R_ / 2)) g2[t] = ((const u64*)gamma)[t];
    __syncthreads();

    const int e = blockIdx.x * 256 + t;
    if (e >= E_) return;

    const int I = eidx[e];
    const int J = eidx[(size_t)E_ + e];

    #pragma unroll 1
    for (int b = 0; b < 2; b++) {
        const ulonglong2* ar = (const ulonglong2*)&g_a[((size_t)b * N_ + I) * R_];
        const ulonglong2* br = (const ulonglong2*)&g_b[((size_t)b * N_ + J) * R_];
        u64 p2[8];
        #pragma unroll
        for (int q = 0; q < 4; q++) {
            ulonglong2 av = ar[q], bv = br[q];
            p2[2*q]     = mm2(av.x, bv.x);
            p2[2*q + 1] = mm2(av.y, bv.y);
        }
        float* ob = out + (size_t)b * L_ * E_ + e;
        #pragma unroll
        for (int l = 0; l < L_; l++) {
            u64 acc = 0ull;
            #pragma unroll
            for (int r = 0; r < 8; r++)
                acc = ff2(g2[l * 8 + r], p2[r], acc);
            float lo, hi; unpk(acc, lo, hi);
            stcs(ob + (size_t)l * E_, lo + hi);
        }
    }
}

extern "C" void kernel_launch(void* const* d_in, const int* in_sizes, int n_in,
                              void* d_out, int out_size) {
    const float* X    = (const float*)d_in[0];
    const int*   eidx = (const int*)d_in[1];           // int32 (jax demotes int64)
    const float* W1s  = (const float*)d_in[2];
    const float* b1s  = (const float*)d_in[3];
    const float* W2s  = (const float*)d_in[4];
    const float* b2s  = (const float*)d_in[5];
    const float* W1d  = (const float*)d_in[6];
    const float* b1d  = (const float*)d_in[7];
    const float* W2d  = (const float*)d_in[8];
    const float* b2d  = (const float*)d_in[9];
    const float* gam  = (const float*)d_in[10];
    float* out = (float*)d_out;

    dim3 g1((B_ * N_ + 127) / 128, 2);
    mlp_kernel<<<g1, 128>>>(X, W1s, b1s, W2s, b2s, W1d, b1d, W2d, b2d);

    edge_kernel<<<(E_ + 255) / 256, 256>>>(eidx, gam, out);
}